// round 3
// baseline (speedup 1.0000x reference)
#include <cuda_runtime.h>
#include <math.h>

#define Dd   512
#define Hh   1024
#define Bb   4
#define Ss   4096
#define Cc   64
#define NCH  64           // S / CHUNK
#define Mm   256          // B * CHUNK rows per chunk
#define SCALEC (2.0f/131072.0f)   // 2 / (B*C*D)

typedef unsigned long long u64;

// ---------------- persistent device scratch (no allocations allowed) --------
__device__ float g_k[NCH*Mm*Dd];     // chunked [n, B*C, D]
__device__ float g_v[NCH*Mm*Dd];
__device__ float g_q[NCH*Mm*Dd];
__device__ float g_y[NCH*Mm*Dd];
__device__ float g_W1e[Hh*Dd];       // Wm1 + d1
__device__ float g_W2e[Dd*Hh];       // Wm2 + d2
__device__ float g_d1[Hh*Dd];
__device__ float g_d2[Dd*Hh];
__device__ float g_m1[Hh*Dd];
__device__ float g_m2[Dd*Hh];
__device__ float g_pre1[Mm*Hh];
__device__ float g_a1[Mm*Hh];
__device__ float g_db2[Mm*Dd];
__device__ float g_db1[Mm*Hh];
__device__ float g_hbuf[Mm*Hh];
__device__ float g_gates[3*NCH];     // decay[64], lr[64], eta[64]

__device__ __forceinline__ float sigmoidf_(float x){ return 1.0f/(1.0f + expf(-x)); }
__device__ __forceinline__ float siluf_(float x){ return x * sigmoidf_(x); }
__device__ __forceinline__ float dsiluf_(float x){ float s = sigmoidf_(x); return s*(1.0f + x*(1.0f - s)); }
__device__ __forceinline__ float clip1f_(float x){ return fminf(1.0f, fmaxf(-1.0f, x)); }

// ---------------- packed f32x2 helpers (Blackwell FFMA2 path) ----------------
__device__ __forceinline__ u64 ffma2_(u64 a, u64 b, u64 c){
    u64 d; asm("fma.rn.f32x2 %0, %1, %2, %3;" : "=l"(d) : "l"(a), "l"(b), "l"(c)); return d;
}
__device__ __forceinline__ u64 pack2_(float x){
    u64 d; asm("mov.b64 %0, {%1, %1};" : "=l"(d) : "f"(x)); return d;
}
__device__ __forceinline__ float2 unpack2_(u64 v){
    float2 f; asm("mov.b64 {%0, %1}, %2;" : "=f"(f.x), "=f"(f.y) : "l"(v)); return f;
}

// ---------------- generic TMxTNx16 SGEMM tile core ---------------------------
// LAYOUT 0 (NT): C[m,n] = sum_k A[m,k] * B[n,k]
// LAYOUT 1 (NN): C[m,n] = sum_k A[m,k] * B[k,n]
// LAYOUT 2 (TN): C[m,n] = sum_k A[k,m] * B[k,n]
// blockDim = (TN/4, TM/4); each thread computes a 4x4 micro-tile held as
// 4x2 packed f32x2 accumulators.
template<int LAYOUT, int TM, int TN>
__device__ __forceinline__ void gemm_block(
    const float* __restrict__ A, const float* __restrict__ B,
    int K, int lda, int ldb, int m0, int n0, u64 acc[4][2])
{
    constexpr int THREADS = (TM/4)*(TN/4);
    __shared__ __align__(16) float As[16][TM+4];
    __shared__ __align__(16) float Bs[16][TN+4];
    const int tx = threadIdx.x, ty = threadIdx.y;
    const int tid = ty * (TN/4) + tx;

    for (int k0 = 0; k0 < K; k0 += 16) {
        // ---- load A tile into As[k][m]
        if (LAYOUT == 0 || LAYOUT == 1) {           // A[m,k] row-major
            #pragma unroll
            for (int i = tid; i < TM*4; i += THREADS) {
                int row = i >> 2, kq = (i & 3) * 4;
                float4 av = *(const float4*)&A[(size_t)(m0 + row) * lda + k0 + kq];
                As[kq+0][row]=av.x; As[kq+1][row]=av.y;
                As[kq+2][row]=av.z; As[kq+3][row]=av.w;
            }
        } else {                                    // A[k,m] row-major
            #pragma unroll
            for (int i = tid; i < TM*4; i += THREADS) {
                int kr = i / (TM/4), mq = (i % (TM/4)) * 4;
                *(float4*)&As[kr][mq] = *(const float4*)&A[(size_t)(k0+kr)*lda + m0 + mq];
            }
        }
        // ---- load B tile into Bs[k][n]
        if (LAYOUT == 0) {                          // B[n,k] row-major
            #pragma unroll
            for (int i = tid; i < TN*4; i += THREADS) {
                int row = i >> 2, kq = (i & 3) * 4;
                float4 bv = *(const float4*)&B[(size_t)(n0 + row) * ldb + k0 + kq];
                Bs[kq+0][row]=bv.x; Bs[kq+1][row]=bv.y;
                Bs[kq+2][row]=bv.z; Bs[kq+3][row]=bv.w;
            }
        } else {                                    // B[k,n] row-major
            #pragma unroll
            for (int i = tid; i < TN*4; i += THREADS) {
                int kr = i / (TN/4), nq = (i % (TN/4)) * 4;
                *(float4*)&Bs[kr][nq] = *(const float4*)&B[(size_t)(k0+kr)*ldb + n0 + nq];
            }
        }
        __syncthreads();
        #pragma unroll
        for (int kk = 0; kk < 16; kk++) {
            float4 a4 = *(const float4*)&As[kk][ty*4];
            ulonglong2 b2 = *(const ulonglong2*)&Bs[kk][tx*4];
            u64 ap0 = pack2_(a4.x), ap1 = pack2_(a4.y);
            u64 ap2 = pack2_(a4.z), ap3 = pack2_(a4.w);
            acc[0][0] = ffma2_(ap0, b2.x, acc[0][0]);
            acc[0][1] = ffma2_(ap0, b2.y, acc[0][1]);
            acc[1][0] = ffma2_(ap1, b2.x, acc[1][0]);
            acc[1][1] = ffma2_(ap1, b2.y, acc[1][1]);
            acc[2][0] = ffma2_(ap2, b2.x, acc[2][0]);
            acc[2][1] = ffma2_(ap2, b2.y, acc[2][1]);
            acc[3][0] = ffma2_(ap3, b2.x, acc[3][0]);
            acc[3][1] = ffma2_(ap3, b2.y, acc[3][1]);
        }
        __syncthreads();
    }
}

// ---------------- init: reset fast-weight state every launch -----------------
__global__ void init_kernel(const float* __restrict__ Wm1, const float* __restrict__ Wm2)
{
    int i = blockIdx.x * 256 + threadIdx.x;
    if (i < Hh * Dd) {
        g_d1[i] = 0.0f; g_m1[i] = 0.0f; g_W1e[i] = Wm1[i];
        g_d2[i] = 0.0f; g_m2[i] = 0.0f; g_W2e[i] = Wm2[i];
    }
}

// ---------------- projections: k/q/v = x @ W^T, written chunked --------------
__global__ __launch_bounds__(256)
void proj_kernel(const float* __restrict__ x,
                 const float* __restrict__ Wk,
                 const float* __restrict__ Wq,
                 const float* __restrict__ Wv)
{
    const float* B = (blockIdx.z == 0) ? Wk : ((blockIdx.z == 1) ? Wq : Wv);
    float* dst     = (blockIdx.z == 0) ? g_k : ((blockIdx.z == 1) ? g_q : g_v);
    u64 acc[4][2] = {};
    int m0 = blockIdx.y * 64, n0 = blockIdx.x * 64;
    gemm_block<0,64,64>(x, B, Dd, Dd, Dd, m0, n0, acc);
    int mbase = m0 + threadIdx.y * 4;
    int nbase = n0 + threadIdx.x * 4;
    #pragma unroll
    for (int i = 0; i < 4; i++) {
        int m = mbase + i;
        int b = m >> 12, s = m & 4095;
        int tt = s >> 6, c = s & 63;
        int row = (tt * Bb + b) * Cc + c;          // chunked row index
        #pragma unroll
        for (int j2 = 0; j2 < 2; j2++) {
            float2 f = unpack2_(acc[i][j2]);
            *(float2*)&dst[(size_t)row * Dd + nbase + j2*2] = f;
        }
    }
}

// ---------------- per-chunk scalar gates -------------------------------------
__global__ void gates_kernel(const float* __restrict__ x,
                             const float* __restrict__ gdw, const float* __restrict__ gdb,
                             const float* __restrict__ glw, const float* __restrict__ glb,
                             const float* __restrict__ gmw, const float* __restrict__ gmb)
{
    int t = blockIdx.x;
    int tid = threadIdx.x;                          // 256 threads, one per (b,c)
    __shared__ float ws[3][Dd];
    for (int j = tid; j < Dd; j += 256) { ws[0][j] = gdw[j]; ws[1][j] = glw[j]; ws[2][j] = gmw[j]; }
    __syncthreads();
    int b = tid >> 6, c = tid & 63;
    const float* xr = x + ((size_t)b * Ss + t * Cc + c) * Dd;
    float s0 = 0.f, s1 = 0.f, s2 = 0.f;
    for (int j = 0; j < Dd; j++) {
        float xv = xr[j];
        s0 += xv * ws[0][j]; s1 += xv * ws[1][j]; s2 += xv * ws[2][j];
    }
    s0 = sigmoidf_(s0 + gdb[0]); s1 = sigmoidf_(s1 + glb[0]); s2 = sigmoidf_(s2 + gmb[0]);
    __shared__ float red[3][256];
    red[0][tid] = s0; red[1][tid] = s1; red[2][tid] = s2;
    __syncthreads();
    for (int o = 128; o > 0; o >>= 1) {
        if (tid < o) {
            red[0][tid] += red[0][tid+o];
            red[1][tid] += red[1][tid+o];
            red[2][tid] += red[2][tid+o];
        }
        __syncthreads();
    }
    if (tid == 0) {
        g_gates[t]          = red[0][0] * (1.0f/256.0f);
        g_gates[NCH + t]    = red[1][0] * (1.0f/256.0f);
        g_gates[2*NCH + t]  = red[2][0] * (1.0f/256.0f);
    }
}

// ---------------- rowwise L2 normalize for k and q ---------------------------
__global__ void norm_kernel()
{
    float* base = blockIdx.y ? g_q : g_k;
    float* row = base + (size_t)blockIdx.x * Dd;
    int tid = threadIdx.x;                          // 128 threads x float4 = 512
    float4 v = reinterpret_cast<float4*>(row)[tid];
    float s = v.x*v.x + v.y*v.y + v.z*v.z + v.w*v.w;
    #pragma unroll
    for (int o = 16; o > 0; o >>= 1) s += __shfl_xor_sync(0xffffffffu, s, o);
    __shared__ float wsum[4];
    if ((tid & 31) == 0) wsum[tid >> 5] = s;
    __syncthreads();
    float tot = wsum[0] + wsum[1] + wsum[2] + wsum[3];
    float inv = 1.0f / (sqrtf(tot) + 1e-8f);
    v.x *= inv; v.y *= inv; v.z *= inv; v.w *= inv;
    reinterpret_cast<float4*>(row)[tid] = v;
}

// ---------------- chunk-loop GEMM stages -------------------------------------
// EPI 0: pre1 = kt @ W1e^T         -> g_pre1, g_a1=silu           [256,1024]
// EPI 1: pred = a1 @ W2e^T         -> g_db2 = clip(pred-v)*scale  [256, 512]
// EPI 2: db1 = (db2 @ W2e)*silu'   -> g_db1                       [256,1024]
// EPI 5: h = silu(qt @ W1e^T)      -> g_hbuf                      [256,1024]
// EPI 6: y = h @ W2e^T             -> g_y chunk slice             [256, 512]
template<int LAYOUT, int EPI, int TM, int TN>
__global__ void step_gemm(int t)
{
    const float* A; const float* B;
    int K, lda, ldb;
    if      (EPI == 0) { A = g_k + (size_t)t*Mm*Dd; B = g_W1e; K = Dd; lda = Dd; ldb = Dd; }
    else if (EPI == 1) { A = g_a1;                  B = g_W2e; K = Hh; lda = Hh; ldb = Hh; }
    else if (EPI == 2) { A = g_db2;                 B = g_W2e; K = Dd; lda = Dd; ldb = Hh; }
    else if (EPI == 5) { A = g_q + (size_t)t*Mm*Dd; B = g_W1e; K = Dd; lda = Dd; ldb = Dd; }
    else               { A = g_hbuf;                B = g_W2e; K = Hh; lda = Hh; ldb = Hh; }

    u64 acc[4][2] = {};
    int m0 = blockIdx.y * TM, n0 = blockIdx.x * TN;
    gemm_block<LAYOUT,TM,TN>(A, B, K, lda, ldb, m0, n0, acc);

    int mbase = m0 + threadIdx.y * 4;
    int nbase = n0 + threadIdx.x * 4;

    #pragma unroll
    for (int i = 0; i < 4; i++) {
        int m = mbase + i;
        #pragma unroll
        for (int j2 = 0; j2 < 2; j2++) {
            float2 f = unpack2_(acc[i][j2]);
            int n = nbase + j2*2;
            if (EPI == 0) {
                g_pre1[m*Hh + n]   = f.x;  g_pre1[m*Hh + n+1] = f.y;
                g_a1[m*Hh + n]     = siluf_(f.x);
                g_a1[m*Hh + n+1]   = siluf_(f.y);
            } else if (EPI == 1) {
                const float* v = g_v + (size_t)t*Mm*Dd;
                float2 o;
                o.x = clip1f_(f.x - v[m*Dd + n])   * SCALEC;
                o.y = clip1f_(f.y - v[m*Dd + n+1]) * SCALEC;
                *(float2*)&g_db2[m*Dd + n] = o;
            } else if (EPI == 2) {
                float2 o;
                o.x = f.x * dsiluf_(g_pre1[m*Hh + n]);
                o.y = f.y * dsiluf_(g_pre1[m*Hh + n+1]);
                *(float2*)&g_db1[m*Hh + n] = o;
            } else if (EPI == 5) {
                float2 o; o.x = siluf_(f.x); o.y = siluf_(f.y);
                *(float2*)&g_hbuf[m*Hh + n] = o;
            } else {
                float* y = g_y + (size_t)t*Mm*Dd;
                *(float2*)&y[m*Dd + n] = f;
            }
        }
    }
}

// ---------------- merged weight-update kernel (g1->W1e and g2->W2e) ----------
// z==0: g1 = db1^T @ kt  [H,D]:  m0 = by*64 (H), n0 = bx*64 (D)
// z==1: g2 = db2^T @ a1  [D,H]:  m0 = bx*64 (D), n0 = by*64 (H)
__global__ __launch_bounds__(256)
void update_gemm(const float* __restrict__ Wm1, const float* __restrict__ Wm2, int t)
{
    float dec = g_gates[t], lr = g_gates[NCH + t], eta = g_gates[2*NCH + t];
    u64 acc[4][2] = {};

    if (blockIdx.z == 0) {
        int m0 = blockIdx.y * 64, n0 = blockIdx.x * 64;
        gemm_block<2,64,64>(g_db1, g_k + (size_t)t*Mm*Dd, Mm, Hh, Dd, m0, n0, acc);
        int mbase = m0 + threadIdx.y * 4;
        int nbase = n0 + threadIdx.x * 4;
        #pragma unroll
        for (int i = 0; i < 4; i++)
            #pragma unroll
            for (int j2 = 0; j2 < 2; j2++) {
                float2 f = unpack2_(acc[i][j2]);
                #pragma unroll
                for (int u = 0; u < 2; u++) {
                    int idx = (mbase + i)*Dd + nbase + j2*2 + u;
                    float g = clip1f_(u ? f.y : f.x);
                    float mm = eta * g_m1[idx] - lr * g;
                    g_m1[idx] = mm;
                    float dd = (1.0f - dec) * g_d1[idx] + mm;
                    g_d1[idx] = dd;
                    g_W1e[idx] = Wm1[idx] + dd;
                }
            }
    } else {
        int m0 = blockIdx.x * 64, n0 = blockIdx.y * 64;
        gemm_block<2,64,64>(g_db2, g_a1, Mm, Dd, Hh, m0, n0, acc);
        int mbase = m0 + threadIdx.y * 4;
        int nbase = n0 + threadIdx.x * 4;
        #pragma unroll
        for (int i = 0; i < 4; i++)
            #pragma unroll
            for (int j2 = 0; j2 < 2; j2++) {
                float2 f = unpack2_(acc[i][j2]);
                #pragma unroll
                for (int u = 0; u < 2; u++) {
                    int idx = (mbase + i)*Hh + nbase + j2*2 + u;
                    float g = clip1f_(u ? f.y : f.x);
                    float mm = eta * g_m2[idx] - lr * g;
                    g_m2[idx] = mm;
                    float dd = (1.0f - dec) * g_d2[idx] + mm;
                    g_d2[idx] = dd;
                    g_W2e[idx] = Wm2[idx] + dd;
                }
            }
    }
}

// ---------------- final: out = y @ Wout^T (undo chunk permutation) -----------
__global__ __launch_bounds__(256)
void final_kernel(const float* __restrict__ Wout, float* __restrict__ out)
{
    u64 acc[4][2] = {};
    int m0 = blockIdx.y * 64, n0 = blockIdx.x * 64;
    gemm_block<0,64,64>(g_y, Wout, Dd, Dd, Dd, m0, n0, acc);
    int mbase = m0 + threadIdx.y * 4;
    int nbase = n0 + threadIdx.x * 4;
    #pragma unroll
    for (int i = 0; i < 4; i++) {
        int m = mbase + i;
        int tt = m >> 8, b = (m >> 6) & 3, c = m & 63;
        size_t orow = (size_t)b * Ss + tt * Cc + c;
        #pragma unroll
        for (int j2 = 0; j2 < 2; j2++) {
            float2 f = unpack2_(acc[i][j2]);
            *(float2*)&out[orow * Dd + nbase + j2*2] = f;
        }
    }
}

// ---------------- launch ------------------------------------------------------
extern "C" void kernel_launch(void* const* d_in, const int* in_sizes, int n_in,
                              void* d_out, int out_size)
{
    const float* x    = (const float*)d_in[0];
    const float* Wk   = (const float*)d_in[1];
    const float* Wv   = (const float*)d_in[2];
    const float* Wq   = (const float*)d_in[3];
    const float* Wout = (const float*)d_in[4];
    const float* Wm1  = (const float*)d_in[5];
    const float* Wm2  = (const float*)d_in[6];
    const float* gd_w = (const float*)d_in[7];
    const float* gd_b = (const float*)d_in[8];
    const float* gl_w = (const float*)d_in[9];
    const float* gl_b = (const float*)d_in[10];
    const float* gm_w = (const float*)d_in[11];
    const float* gm_b = (const float*)d_in[12];
    float* out = (float*)d_out;

    dim3 thr64(16, 16);     // 64x64 tiles
    dim3 thr3264(16, 8);    // 32x64 tiles
    dim3 thr3232(8, 8);     // 32x32 tiles

    init_kernel<<<(Hh*Dd + 255)/256, 256>>>(Wm1, Wm2);
    proj_kernel<<<dim3(Dd/64, (Bb*Ss)/64, 3), thr64>>>(x, Wk, Wq, Wv);
    gates_kernel<<<NCH, 256>>>(x, gd_w, gd_b, gl_w, gl_b, gm_w, gm_b);
    norm_kernel<<<dim3(Bb*Ss, 2), 128>>>();

    for (int t = 0; t < NCH; t++) {
        step_gemm<0,0,32,64><<<dim3(Hh/64, Mm/32), thr3264>>>(t);  // pre1, a1
        step_gemm<0,1,32,32><<<dim3(Dd/32, Mm/32), thr3232>>>(t);  // pred -> db2
        step_gemm<1,2,32,64><<<dim3(Hh/64, Mm/32), thr3264>>>(t);  // db1 (old W2e)
        update_gemm<<<dim3(8, 16, 2), thr64>>>(Wm1, Wm2, t);       // g1+g2 -> W1e,W2e
        step_gemm<0,5,32,64><<<dim3(Hh/64, Mm/32), thr3264>>>(t);  // h (new W1e)
        step_gemm<0,6,32,32><<<dim3(Dd/32, Mm/32), thr3232>>>(t);  // y (new W2e)
    }

    final_kernel<<<dim3(Dd/64, (Bb*Ss)/64), thr64>>>(Wout, out);
}